// round 13
// baseline (speedup 1.0000x reference)
#include <cuda_runtime.h>
#include <cuda_bf16.h>
#include <cuda_fp16.h>
#include <cstdint>
#include <cstddef>

// Problem constants
#define BB 4
#define SS 2048
#define DD 1024
#define HH 16
#define DKK 64
#define FF 4096
#define MM (BB*SS)          // 8192 rows

// ---------------------------------------------------------------------------
// Scratch (no allocations allowed -> __device__ globals)
// ---------------------------------------------------------------------------
__device__ float g_proj[(size_t)MM*DD];
__device__ float g_x1  [(size_t)MM*DD];
__device__ float g_ff2 [(size_t)MM*DD];

// fp16 single-term GEMM operands
__device__ unsigned short g_ax  [(size_t)MM*DD];     // x        fp16
__device__ unsigned short g_aatt[(size_t)MM*DD];     // attn out fp16
__device__ unsigned short g_ax1 [(size_t)MM*DD];     // x1       fp16
__device__ unsigned short g_aff1[(size_t)MM*FF];     // relu ff1 fp16
__device__ unsigned short g_wq  [(size_t)DD*DD];     // W^T fp16
__device__ unsigned short g_wk  [(size_t)DD*DD];
__device__ unsigned short g_wv  [(size_t)DD*DD];
__device__ unsigned short g_wo  [(size_t)DD*DD];
__device__ unsigned short g_w1  [(size_t)FF*DD];     // [N=F, K=D]
__device__ unsigned short g_w2  [(size_t)DD*FF];     // [N=D, K=F]

// fp16 2-term attention operands
__device__ unsigned short g_qs  [(size_t)MM*2*DD];   // q*1/8 fp16 [hi | lo]
__device__ unsigned short g_ks  [(size_t)MM*2*DD];   // k     fp16 [hi | hi]
__device__ unsigned short g_vs  [(size_t)MM*DD];     // v     fp16 single

// ---------------------------------------------------------------------------
// Helpers
// ---------------------------------------------------------------------------
__device__ __forceinline__ uint32_t smem_u32(const void* p) {
    uint32_t a;
    asm("{ .reg .u64 t; cvta.to.shared.u64 t, %1; cvt.u32.u64 %0, t; }"
        : "=r"(a) : "l"(p));
    return a;
}

__device__ __forceinline__ void cp16(uint32_t dst, const void* src) {
    asm volatile("cp.async.cg.shared.global [%0], [%1], 16;" :: "r"(dst), "l"(src));
}

#define CP_COMMIT() asm volatile("cp.async.commit_group;")
#define CP_WAIT1()  asm volatile("cp.async.wait_group 1;" ::: "memory")

#define LDSM4(r0, r1, r2, r3, addr) \
    asm volatile("ldmatrix.sync.aligned.m8n8.x4.shared.b16 {%0,%1,%2,%3}, [%4];" \
        : "=r"(r0), "=r"(r1), "=r"(r2), "=r"(r3) : "r"(addr))

#define LDSM4T(r0, r1, r2, r3, addr) \
    asm volatile("ldmatrix.sync.aligned.m8n8.x4.trans.shared.b16 {%0,%1,%2,%3}, [%4];" \
        : "=r"(r0), "=r"(r1), "=r"(r2), "=r"(r3) : "r"(addr))

// fp16 MMA
#define MMA16816F(d, a, b0v, b1v) \
    asm volatile("mma.sync.aligned.m16n8k16.row.col.f32.f16.f16.f32 " \
        "{%0,%1,%2,%3}, {%4,%5,%6,%7}, {%8,%9}, {%0,%1,%2,%3};" \
        : "+f"((d)[0]), "+f"((d)[1]), "+f"((d)[2]), "+f"((d)[3]) \
        : "r"((a)[0]), "r"((a)[1]), "r"((a)[2]), "r"((a)[3]), "r"(b0v), "r"(b1v))

__device__ __forceinline__ unsigned short f2h_bits(float f) {
    __half h = __float2half(f);
    return *reinterpret_cast<unsigned short*>(&h);
}
__device__ __forceinline__ void hsplit(float x, unsigned short& h, unsigned short& l) {
    h = f2h_bits(x);
    __half hb = *reinterpret_cast<__half*>(&h);
    l = f2h_bits(x - __half2float(hb));
}

// ---------------------------------------------------------------------------
// fp32 -> fp16 single-term conversion for activations. A[m, K].
// ---------------------------------------------------------------------------
__global__ __launch_bounds__(256) void convert_a_kernel(
    const float* __restrict__ X, unsigned short* __restrict__ A, int K)
{
    size_t idx = (size_t)blockIdx.x * blockDim.x + threadIdx.x;
    size_t total = (size_t)MM * K / 4;
    if (idx >= total) return;
    size_t e = idx * 4;
    float4 v = *(const float4*)(X + e);
    uint2 hp = make_uint2((uint32_t)f2h_bits(v.x) | ((uint32_t)f2h_bits(v.y) << 16),
                          (uint32_t)f2h_bits(v.z) | ((uint32_t)f2h_bits(v.w) << 16));
    *(uint2*)(A + e) = hp;
}

// ---------------------------------------------------------------------------
// W[K,N] fp32 -> B[N, K] fp16 (transposed).
// ---------------------------------------------------------------------------
__global__ __launch_bounds__(256) void convert_w_kernel(
    const float* __restrict__ W, unsigned short* __restrict__ Bm, int K, int N)
{
    __shared__ float tile[32][33];
    const int n0 = blockIdx.x * 32;
    const int k0 = blockIdx.y * 32;
    for (int i = threadIdx.y; i < 32; i += 8)
        tile[i][threadIdx.x] = W[(size_t)(k0 + i) * N + n0 + threadIdx.x];
    __syncthreads();
    for (int i = threadIdx.y; i < 32; i += 8) {
        const int n = n0 + i;
        const int k = k0 + threadIdx.x;
        Bm[(size_t)n * K + k] = f2h_bits(tile[threadIdx.x][i]);
    }
}

// ---------------------------------------------------------------------------
// mma.sync fp16 GEMM: BM=BN=128, BK=64, 3-stage cp.async, 256 threads
// (8 warps 2x4, warp tile 64x32), __launch_bounds__(256, 2).
// ONE __syncthreads per chunk: wait_group 1 -> sync -> prefetch(c+2) ->
// commit -> compute. Prefetch-after-barrier makes the trailing sync
// unnecessary (stage (c+2)%3 == (c-1)%3, whose readers all passed the
// barrier). Unconditional COMMIT keeps wait_group arithmetic exact.
// C = A[M,K] @ B[N,K]^T + bias. Epilogue modes:
//   0: fp32 C = acc + bias                  -> Cf[m][N]
//   1: relu -> fp16                         -> Cs[m][N]
//   2: (acc+bias)*0.125 -> fp16 [hi|lo] [Q] -> Cs[m][2N]
//   3: fp16 [hi|hi]                     [K] -> Cs[m][2N]
//   4: fp16 single                      [V] -> Cs[m][N]
// ---------------------------------------------------------------------------
#define BK 64
#define NSTAGE 3
#define ROWB 144                      // 128B data + 16B pad (144 % 128 == 16)
#define B_OFF (128*ROWB)              // 18432
#define STG_B (2*B_OFF)               // 36864
#define GEMM_SMEM (NSTAGE*STG_B)      // 110592 (x2 CTAs = 221KB <= 228KB/SM)

__global__ __launch_bounds__(256, 2) void mma_gemm_kernel(
    const unsigned short* __restrict__ Au, const unsigned short* __restrict__ Bu,
    const float* __restrict__ bias, float* __restrict__ Cf,
    unsigned short* __restrict__ Cs, int N, int K2, int mode)
{
    extern __shared__ char smem[];
    const uint32_t sb = smem_u32(smem);
    const int tid = threadIdx.x;
    const int wid = tid >> 5, lane = tid & 31;
    const int wm = wid >> 2, wn = wid & 3;
    const int mb = blockIdx.y, nb = blockIdx.x;

    // load mapping: 2 threads per 128B row; each thread 4x16B chunks
    const int r0 = tid >> 1, hf = tid & 1;
    const unsigned short* aS = Au + ((size_t)(mb * 128) + r0) * K2 + hf * 32;
    const unsigned short* bS = Bu + ((size_t)(nb * 128) + r0) * K2 + hf * 32;
    const uint32_t dOff = (uint32_t)(r0 * ROWB + hf * 64);

    float acc[4][4][4];
    #pragma unroll
    for (int i = 0; i < 4; i++)
        #pragma unroll
        for (int j = 0; j < 4; j++)
            #pragma unroll
            for (int r = 0; r < 4; r++) acc[i][j][r] = 0.f;

    const int nc = K2 / BK;

    auto LOAD = [&](int s, int c) {
        const uint32_t d = sb + s * STG_B + dOff;
        const unsigned short* a = aS + (size_t)c * BK;
        const unsigned short* b = bS + (size_t)c * BK;
        #pragma unroll
        for (int i = 0; i < 4; i++) {
            cp16(d + i * 16,         a + i * 8);
            cp16(d + B_OFF + i * 16, b + i * 8);
        }
    };

    LOAD(0, 0); CP_COMMIT();
    if (nc > 1) LOAD(1, 1);
    CP_COMMIT();

    const uint32_t aRow = (uint32_t)(wm * 64 + (lane & 15));
    const uint32_t aK   = ((lane >> 4) & 1) * 16;
    const uint32_t bRow = (uint32_t)(wn * 32 + ((lane >> 4) & 1) * 8 + (lane & 7));
    const uint32_t bK   = ((lane >> 3) & 1) * 16;

    for (int c = 0; c < nc; c++) {
        CP_WAIT1();
        __syncthreads();
        if (c + 2 < nc) LOAD((c + 2) % NSTAGE, c + 2);
        CP_COMMIT();
        const uint32_t base = sb + (c % NSTAGE) * STG_B;
        #pragma unroll
        for (int ks = 0; ks < 4; ks++) {
            uint32_t af[4][4], bf[2][4];
            #pragma unroll
            for (int mt = 0; mt < 4; mt++) {
                const uint32_t ad = base + (aRow + mt * 16) * ROWB + ks * 32 + aK;
                LDSM4(af[mt][0], af[mt][1], af[mt][2], af[mt][3], ad);
            }
            #pragma unroll
            for (int j = 0; j < 2; j++) {
                const uint32_t bd = base + B_OFF + (bRow + j * 16) * ROWB + ks * 32 + bK;
                LDSM4(bf[j][0], bf[j][1], bf[j][2], bf[j][3], bd);
            }
            #pragma unroll
            for (int mt = 0; mt < 4; mt++)
                #pragma unroll
                for (int nt = 0; nt < 4; nt++)
                    MMA16816F(acc[mt][nt], af[mt],
                              bf[nt >> 1][(nt & 1) * 2], bf[nt >> 1][(nt & 1) * 2 + 1]);
        }
    }

    // ---------------- epilogue (fused conversions) ----------------
    const int row0 = mb * 128 + wm * 64 + (lane >> 2);
    const int col0 = nb * 128 + wn * 32 + (lane & 3) * 2;
    #pragma unroll
    for (int mt = 0; mt < 4; mt++) {
        const int r1 = row0 + mt * 16;
        const int r2 = r1 + 8;
        #pragma unroll
        for (int nt = 0; nt < 4; nt++) {
            const int cn = col0 + nt * 8;
            const float bx = __ldg(bias + cn), by = __ldg(bias + cn + 1);
            float o10 = acc[mt][nt][0] + bx, o11 = acc[mt][nt][1] + by;
            float o20 = acc[mt][nt][2] + bx, o21 = acc[mt][nt][3] + by;
            if (mode == 0) {
                *(float2*)(Cf + (size_t)r1 * N + cn) = make_float2(o10, o11);
                *(float2*)(Cf + (size_t)r2 * N + cn) = make_float2(o20, o21);
            } else if (mode == 1) {
                o10 = fmaxf(o10, 0.f); o11 = fmaxf(o11, 0.f);
                o20 = fmaxf(o20, 0.f); o21 = fmaxf(o21, 0.f);
                *(uint32_t*)(Cs + (size_t)r1 * N + cn) =
                    (uint32_t)f2h_bits(o10) | ((uint32_t)f2h_bits(o11) << 16);
                *(uint32_t*)(Cs + (size_t)r2 * N + cn) =
                    (uint32_t)f2h_bits(o20) | ((uint32_t)f2h_bits(o21) << 16);
            } else if (mode == 4) {
                *(uint32_t*)(Cs + (size_t)r1 * N + cn) =
                    (uint32_t)f2h_bits(o10) | ((uint32_t)f2h_bits(o11) << 16);
                *(uint32_t*)(Cs + (size_t)r2 * N + cn) =
                    (uint32_t)f2h_bits(o20) | ((uint32_t)f2h_bits(o21) << 16);
            } else if (mode == 2) {
                o10 *= 0.125f; o11 *= 0.125f; o20 *= 0.125f; o21 *= 0.125f;
                unsigned short h0, l0, h1, l1;
                hsplit(o10, h0, l0); hsplit(o11, h1, l1);
                unsigned short* p = Cs + (size_t)r1 * (2 * N) + cn;
                *(uint32_t*)p       = (uint32_t)h0 | ((uint32_t)h1 << 16);
                *(uint32_t*)(p + N) = (uint32_t)l0 | ((uint32_t)l1 << 16);
                hsplit(o20, h0, l0); hsplit(o21, h1, l1);
                p = Cs + (size_t)r2 * (2 * N) + cn;
                *(uint32_t*)p       = (uint32_t)h0 | ((uint32_t)h1 << 16);
                *(uint32_t*)(p + N) = (uint32_t)l0 | ((uint32_t)l1 << 16);
            } else {
                uint32_t w1v = (uint32_t)f2h_bits(o10) | ((uint32_t)f2h_bits(o11) << 16);
                unsigned short* p = Cs + (size_t)r1 * (2 * N) + cn;
                *(uint32_t*)p       = w1v;
                *(uint32_t*)(p + N) = w1v;
                uint32_t w2v = (uint32_t)f2h_bits(o20) | ((uint32_t)f2h_bits(o21) << 16);
                p = Cs + (size_t)r2 * (2 * N) + cn;
                *(uint32_t*)p       = w2v;
                *(uint32_t*)(p + N) = w2v;
            }
        }
    }
}

// ---------------------------------------------------------------------------
// Tensor-core flash attention, fp16 2-term (unchanged from R12).
// ---------------------------------------------------------------------------
#define AQROWB 272
#define AVROWB 144
#define ATT2_SMEM (2*64*AQROWB + 64*AVROWB)   // 44032

__global__ __launch_bounds__(128, 2) void attn_tc_kernel(
    const unsigned short* __restrict__ Qg, const unsigned short* __restrict__ Kg,
    const unsigned short* __restrict__ Vg, unsigned short* __restrict__ Aout)
{
    extern __shared__ char sm8[];
    char* Qs = sm8;
    char* Ks = Qs + 64 * AQROWB;
    char* Vs = Ks + 64 * AQROWB;
    const uint32_t qsb = smem_u32(Qs), ksb = smem_u32(Ks);
    const uint32_t vsb = smem_u32(Vs);

    const int tid = threadIdx.x, wid = tid >> 5, lane = tid & 31;
    const int q0 = blockIdx.x * 64;
    const int b = blockIdx.y >> 4, h = blockIdx.y & 15;
    const size_t bS = (size_t)b * SS;

    {
        const int r = tid >> 1, half = tid & 1;
        const unsigned short* src = Qg + (bS + q0 + r) * (size_t)(2 * DD)
                                       + half * DD + h * 64;
        char* drow = Qs + r * AQROWB + half * 128;
        #pragma unroll
        for (int off = 0; off < 8; off++)
            *(uint4*)(drow + off * 16) = *(const uint4*)(src + off * 8);
    }
    __syncthreads();

    uint32_t qf[8][4];
    {
        const uint32_t ab = qsb + (wid * 16 + (lane & 15)) * AQROWB + ((lane >> 4) & 1) * 16;
        #pragma unroll
        for (int ks = 0; ks < 8; ks++)
            LDSM4(qf[ks][0], qf[ks][1], qf[ks][2], qf[ks][3], ab + ks * 32);
    }

    const uint32_t bRow = ((lane >> 4) & 1) * 8 + (lane & 7);
    const uint32_t bK   = ((lane >> 3) & 1) * 16;
    const uint32_t vLn  = (lane & 15);
    const uint32_t vCo  = ((lane >> 4) & 1) * 16;

    float O[8][4];
    #pragma unroll
    for (int j = 0; j < 8; j++)
        #pragma unroll
        for (int r = 0; r < 4; r++) O[j][r] = 0.f;
    float m0 = -1e30f, m1 = -1e30f, l0 = 0.f, l1 = 0.f;

    const int r0l = wid * 16 + (lane >> 2);
    const int r1l = r0l + 8;

    for (int kt = 0; kt <= blockIdx.x; kt++) {
        const int k0 = kt * 64;
        __syncthreads();
        {
            const int r = tid >> 1, half = tid & 1;
            const unsigned short* ksrc = Kg + (bS + k0 + r) * (size_t)(2 * DD)
                                            + half * DD + h * 64;
            char* krow = Ks + r * AQROWB + half * 128;
            #pragma unroll
            for (int off = 0; off < 8; off++)
                *(uint4*)(krow + off * 16) = *(const uint4*)(ksrc + off * 8);
            const unsigned short* vsrc = Vg + (bS + k0 + r) * (size_t)DD
                                            + h * 64 + half * 32;
            char* vrow = Vs + r * AVROWB + half * 64;
            #pragma unroll
            for (int off = 0; off < 4; off++)
                *(uint4*)(vrow + off * 16) = *(const uint4*)(vsrc + off * 8);
        }
        __syncthreads();

        float s[8][4];
        #pragma unroll
        for (int j = 0; j < 8; j++)
            #pragma unroll
            for (int r = 0; r < 4; r++) s[j][r] = 0.f;
        #pragma unroll
        for (int ks = 0; ks < 8; ks++) {
            #pragma unroll
            for (int j16 = 0; j16 < 4; j16++) {
                uint32_t kf0, kf1, kf2, kf3;
                LDSM4(kf0, kf1, kf2, kf3,
                      ksb + (j16 * 16 + bRow) * AQROWB + ks * 32 + bK);
                MMA16816F(s[2 * j16],     qf[ks], kf0, kf1);
                MMA16816F(s[2 * j16 + 1], qf[ks], kf2, kf3);
            }
        }

        if (kt == (int)blockIdx.x) {
            #pragma unroll
            for (int j = 0; j < 8; j++) {
                const int c = j * 8 + 2 * (lane & 3);
                if (c     > r0l) s[j][0] = -1e30f;
                if (c + 1 > r0l) s[j][1] = -1e30f;
                if (c     > r1l) s[j][2] = -1e30f;
                if (c + 1 > r1l) s[j][3] = -1e30f;
            }
        }

        float mx0 = -1e30f, mx1 = -1e30f;
        #pragma unroll
        for (int j = 0; j < 8; j++) {
            mx0 = fmaxf(mx0, fmaxf(s[j][0], s[j][1]));
            mx1 = fmaxf(mx1, fmaxf(s[j][2], s[j][3]));
        }
        mx0 = fmaxf(mx0, __shfl_xor_sync(0xffffffffu, mx0, 1));
        mx0 = fmaxf(mx0, __shfl_xor_sync(0xffffffffu, mx0, 2));
        mx1 = fmaxf(mx1, __shfl_xor_sync(0xffffffffu, mx1, 1));
        mx1 = fmaxf(mx1, __shfl_xor_sync(0xffffffffu, mx1, 2));
        const float mn0 = fmaxf(m0, mx0), mn1 = fmaxf(m1, mx1);
        const float cr0 = __expf(m0 - mn0), cr1 = __expf(m1 - mn1);
        m0 = mn0; m1 = mn1;
        float sum0 = 0.f, sum1 = 0.f;
        #pragma unroll
        for (int j = 0; j < 8; j++) {
            s[j][0] = __expf(s[j][0] - mn0);
            s[j][1] = __expf(s[j][1] - mn0);
            s[j][2] = __expf(s[j][2] - mn1);
            s[j][3] = __expf(s[j][3] - mn1);
            sum0 += s[j][0] + s[j][1];
            sum1 += s[j][2] + s[j][3];
        }
        sum0 += __shfl_xor_sync(0xffffffffu, sum0, 1);
        sum0 += __shfl_xor_sync(0xffffffffu, sum0, 2);
        sum1 += __shfl_xor_sync(0xffffffffu, sum1, 1);
        sum1 += __shfl_xor_sync(0xffffffffu, sum1, 2);
        l0 = l0 * cr0 + sum0;
        l1 = l1 * cr1 + sum1;
        #pragma unroll
        for (int j = 0; j < 8; j++) {
            O[j][0] *= cr0; O[j][1] *= cr0;
            O[j][2] *= cr1; O[j][3] *= cr1;
        }

        uint32_t phi[4][4], plo[4][4];
        #pragma unroll
        for (int ks2 = 0; ks2 < 4; ks2++) {
            const int j0 = 2 * ks2, j1 = j0 + 1;
            unsigned short h00, l00, h01, l01, h10, l10, h11, l11;
            hsplit(s[j0][0], h00, l00); hsplit(s[j0][1], h01, l01);
            phi[ks2][0] = (uint32_t)h00 | ((uint32_t)h01 << 16);
            plo[ks2][0] = (uint32_t)l00 | ((uint32_t)l01 << 16);
            hsplit(s[j0][2], h10, l10); hsplit(s[j0][3], h11, l11);
            phi[ks2][1] = (uint32_t)h10 | ((uint32_t)h11 << 16);
            plo[ks2][1] = (uint32_t)l10 | ((uint32_t)l11 << 16);
            hsplit(s[j1][0], h00, l00); hsplit(s[j1][1], h01, l01);
            phi[ks2][2] = (uint32_t)h00 | ((uint32_t)h01 << 16);
            plo[ks2][2] = (uint32_t)l00 | ((uint32_t)l01 << 16);
            hsplit(s[j1][2], h10, l10); hsplit(s[j1][3], h11, l11);
            phi[ks2][3] = (uint32_t)h10 | ((uint32_t)h11 << 16);
            plo[ks2][3] = (uint32_t)l10 | ((uint32_t)l11 << 16);
        }

        #pragma unroll
        for (int ks2 = 0; ks2 < 4; ks2++) {
            const uint32_t rowOff = (ks2 * 16 + vLn);
            #pragma unroll
            for (int dj = 0; dj < 4; dj++) {
                uint32_t v0, v1, v2, v3;
                LDSM4T(v0, v1, v2, v3, vsb + rowOff * AVROWB + dj * 32 + vCo);
                MMA16816F(O[2 * dj],     phi[ks2], v0, v1);
                MMA16816F(O[2 * dj + 1], phi[ks2], v2, v3);
                MMA16816F(O[2 * dj],     plo[ks2], v0, v1);
                MMA16816F(O[2 * dj + 1], plo[ks2], v2, v3);
            }
        }
    }

    const float inv0 = 1.f / l0, inv1 = 1.f / l1;
    const size_t m0g = bS + (q0 + r0l);
    const size_t m1g = m0g + 8;
    const int cb = h * 64 + 2 * (lane & 3);
    unsigned short* out0 = Aout + m0g * (size_t)DD + cb;
    unsigned short* out1 = Aout + m1g * (size_t)DD + cb;
    #pragma unroll
    for (int j = 0; j < 8; j++) {
        const int d = j * 8;
        *(uint32_t*)(out0 + d) = (uint32_t)f2h_bits(O[j][0] * inv0)
                               | ((uint32_t)f2h_bits(O[j][1] * inv0) << 16);
        *(uint32_t*)(out1 + d) = (uint32_t)f2h_bits(O[j][2] * inv1)
                               | ((uint32_t)f2h_bits(O[j][3] * inv1) << 16);
    }
}

// ---------------------------------------------------------------------------
// out = LayerNorm(x + y) * gamma + beta; optional fused fp16 conversion
// ---------------------------------------------------------------------------
__device__ __forceinline__ float block_sum(float v, float* sh)
{
    const int lane = threadIdx.x & 31, w = threadIdx.x >> 5;
    #pragma unroll
    for (int o = 16; o; o >>= 1) v += __shfl_xor_sync(0xffffffffu, v, o);
    if (lane == 0) sh[w] = v;
    __syncthreads();
    float r = (lane < 8) ? sh[lane] : 0.f;
    #pragma unroll
    for (int o = 4; o; o >>= 1) r += __shfl_xor_sync(0xffffffffu, r, o);
    if (threadIdx.x == 0) sh[0] = r;
    __syncthreads();
    r = sh[0];
    __syncthreads();
    return r;
}

__global__ __launch_bounds__(256) void add_ln_kernel(
    const float* __restrict__ X, const float* __restrict__ Y,
    const float* __restrict__ g, const float* __restrict__ bta,
    float* __restrict__ out, unsigned short* __restrict__ As)
{
    __shared__ float sh[32];
    const size_t row = blockIdx.x;
    const int t = threadIdx.x;
    const float4 xv = ((const float4*)(X + row * DD))[t];
    const float4 yv = ((const float4*)(Y + row * DD))[t];
    float v0 = xv.x + yv.x, v1 = xv.y + yv.y, v2 = xv.z + yv.z, v3 = xv.w + yv.w;
    const float mean = block_sum(v0 + v1 + v2 + v3, sh) * (1.f / DD);
    const float d0 = v0 - mean, d1 = v1 - mean, d2 = v2 - mean, d3 = v3 - mean;
    const float var = block_sum(d0*d0 + d1*d1 + d2*d2 + d3*d3, sh) * (1.f / DD);
    const float inv = rsqrtf(var + 1e-5f);
    const float4 gv = ((const float4*)g)[t];
    const float4 bv = ((const float4*)bta)[t];
    float4 o;
    o.x = d0 * inv * gv.x + bv.x;
    o.y = d1 * inv * gv.y + bv.y;
    o.z = d2 * inv * gv.z + bv.z;
    o.w = d3 * inv * gv.w + bv.w;
    ((float4*)(out + row * DD))[t] = o;
    if (As) {
        uint2 hp = make_uint2((uint32_t)f2h_bits(o.x) | ((uint32_t)f2h_bits(o.y) << 16),
                              (uint32_t)f2h_bits(o.z) | ((uint32_t)f2h_bits(o.w) << 16));
        *(uint2*)(As + row * (size_t)DD + t * 4) = hp;
    }
}

// ---------------------------------------------------------------------------
// Launcher
// ---------------------------------------------------------------------------
extern "C" void kernel_launch(void* const* d_in, const int* in_sizes, int n_in,
                              void* d_out, int out_size)
{
    (void)in_sizes; (void)n_in; (void)out_size;
    const float* x  = (const float*)d_in[0];
    const float* Wq = (const float*)d_in[2];
    const float* bq = (const float*)d_in[3];
    const float* Wk = (const float*)d_in[4];
    const float* bk = (const float*)d_in[5];
    const float* Wv = (const float*)d_in[6];
    const float* bv = (const float*)d_in[7];
    const float* Wo = (const float*)d_in[8];
    const float* bo = (const float*)d_in[9];
    const float* g1 = (const float*)d_in[10];
    const float* b1 = (const float*)d_in[11];
    const float* W1 = (const float*)d_in[12];
    const float* c1 = (const float*)d_in[13];
    const float* W2 = (const float*)d_in[14];
    const float* c2 = (const float*)d_in[15];
    const float* g2 = (const float*)d_in[16];
    const float* b2 = (const float*)d_in[17];
    float* out = (float*)d_out;

    float *proj, *x1, *ff2;
    cudaGetSymbolAddress((void**)&proj, g_proj);
    cudaGetSymbolAddress((void**)&x1,   g_x1);
    cudaGetSymbolAddress((void**)&ff2,  g_ff2);

    unsigned short *ax, *qs, *ks, *vs, *aatt, *ax1, *aff1;
    unsigned short *wq2, *wk2, *wv2, *wo2, *w12, *w22;
    cudaGetSymbolAddress((void**)&ax,   g_ax);
    cudaGetSymbolAddress((void**)&qs,   g_qs);
    cudaGetSymbolAddress((void**)&ks,   g_ks);
    cudaGetSymbolAddress((void**)&vs,   g_vs);
    cudaGetSymbolAddress((void**)&aatt, g_aatt);
    cudaGetSymbolAddress((void**)&ax1,  g_ax1);
    cudaGetSymbolAddress((void**)&aff1, g_aff1);
    cudaGetSymbolAddress((void**)&wq2,  g_wq);
    cudaGetSymbolAddress((void**)&wk2,  g_wk);
    cudaGetSymbolAddress((void**)&wv2,  g_wv);
    cudaGetSymbolAddress((void**)&wo2,  g_wo);
    cudaGetSymbolAddress((void**)&w12,  g_w1);
    cudaGetSymbolAddress((void**)&w22,  g_w2);

    cudaFuncSetAttribute(mma_gemm_kernel,
                         cudaFuncAttributeMaxDynamicSharedMemorySize, GEMM_SMEM);
    cudaFuncSetAttribute(attn_tc_kernel,
                         cudaFuncAttributeMaxDynamicSharedMemorySize, ATT2_SMEM);

    const dim3 blk(256);
    const dim3 wblk(32, 8);
    const dim3 gD(DD/128, MM/128);       // N=1024 GEMMs
    const dim3 gF(FF/128, MM/128);       // N=4096 GEMM

    convert_w_kernel<<<dim3(DD/32, DD/32), wblk>>>(Wq, wq2, DD, DD);
    convert_w_kernel<<<dim3(DD/32, DD/32), wblk>>>(Wk, wk2, DD, DD);
    convert_w_kernel<<<dim3(DD/32, DD/32), wblk>>>(Wv, wv2, DD, DD);
    convert_w_kernel<<<dim3(DD/32, DD/32), wblk>>>(Wo, wo2, DD, DD);
    convert_a_kernel<<<(int)(((size_t)MM*DD/4 + 255)/256), blk>>>(x, ax, DD);

    // QKV projections -> fp16 attention layouts
    mma_gemm_kernel<<<gD, blk, GEMM_SMEM>>>(ax, wq2, bq, nullptr, qs, DD, DD, 2);
    mma_gemm_kernel<<<gD, blk, GEMM_SMEM>>>(ax, wk2, bk, nullptr, ks, DD, DD, 3);
    mma_gemm_kernel<<<gD, blk, GEMM_SMEM>>>(ax, wv2, bv, nullptr, vs, DD, DD, 4);

    // attention (fp16 2-term, writes fp16 single A)
    attn_tc_kernel<<<dim3(SS/64, BB*HH), 128, ATT2_SMEM>>>(qs, ks, vs, aatt);

    // output projection + residual LN (fused fp16 conversion of x1)
    mma_gemm_kernel<<<gD, blk, GEMM_SMEM>>>(aatt, wo2, bo, proj, nullptr, DD, DD, 0);
    add_ln_kernel<<<MM, blk>>>(x, proj, g1, b1, x1, ax1);

    // FFN
    convert_w_kernel<<<dim3(FF/32, DD/32), wblk>>>(W1, w12, DD, FF);
    mma_gemm_kernel<<<gF, blk, GEMM_SMEM>>>(ax1, w12, c1, nullptr, aff1, FF, DD, 1);
    convert_w_kernel<<<dim3(DD/32, FF/32), wblk>>>(W2, w22, FF, DD);
    mma_gemm_kernel<<<gD, blk, GEMM_SMEM>>>(aff1, w22, c2, ff2, nullptr, DD, FF, 0);
    add_ln_kernel<<<MM, blk>>>(x1, ff2, g2, b2, out, nullptr);
}

// round 14
// speedup vs baseline: 1.1157x; 1.1157x over previous
#include <cuda_runtime.h>
#include <cuda_bf16.h>
#include <cuda_fp16.h>
#include <cstdint>
#include <cstddef>

// Problem constants
#define BB 4
#define SS 2048
#define DD 1024
#define HH 16
#define DKK 64
#define FF 4096
#define MM (BB*SS)          // 8192 rows

// ---------------------------------------------------------------------------
// Scratch (no allocations allowed -> __device__ globals)
// ---------------------------------------------------------------------------
__device__ float g_proj[(size_t)MM*DD];
__device__ float g_x1  [(size_t)MM*DD];
__device__ float g_ff2 [(size_t)MM*DD];

// fp16 single-term GEMM operands
__device__ unsigned short g_ax  [(size_t)MM*DD];     // x        fp16
__device__ unsigned short g_aatt[(size_t)MM*DD];     // attn out fp16
__device__ unsigned short g_ax1 [(size_t)MM*DD];     // x1       fp16
__device__ unsigned short g_aff1[(size_t)MM*FF];     // relu ff1 fp16
__device__ unsigned short g_wq  [(size_t)DD*DD];     // W^T fp16
__device__ unsigned short g_wk  [(size_t)DD*DD];
__device__ unsigned short g_wv  [(size_t)DD*DD];
__device__ unsigned short g_wo  [(size_t)DD*DD];
__device__ unsigned short g_w1  [(size_t)FF*DD];     // [N=F, K=D]
__device__ unsigned short g_w2  [(size_t)DD*FF];     // [N=D, K=F]

// fp16 2-term attention operands
__device__ unsigned short g_qs  [(size_t)MM*2*DD];   // q*1/8 fp16 [hi | lo]
__device__ unsigned short g_ks  [(size_t)MM*2*DD];   // k     fp16 [hi | hi]
__device__ unsigned short g_vs  [(size_t)MM*DD];     // v     fp16 single

// ---------------------------------------------------------------------------
// Helpers
// ---------------------------------------------------------------------------
__device__ __forceinline__ uint32_t smem_u32(const void* p) {
    uint32_t a;
    asm("{ .reg .u64 t; cvta.to.shared.u64 t, %1; cvt.u32.u64 %0, t; }"
        : "=r"(a) : "l"(p));
    return a;
}

__device__ __forceinline__ void cp16(uint32_t dst, const void* src) {
    asm volatile("cp.async.cg.shared.global [%0], [%1], 16;" :: "r"(dst), "l"(src));
}

#define CP_COMMIT() asm volatile("cp.async.commit_group;")
#define CP_WAIT3()  asm volatile("cp.async.wait_group 3;" ::: "memory")

#define LDSM4(r0, r1, r2, r3, addr) \
    asm volatile("ldmatrix.sync.aligned.m8n8.x4.shared.b16 {%0,%1,%2,%3}, [%4];" \
        : "=r"(r0), "=r"(r1), "=r"(r2), "=r"(r3) : "r"(addr))

#define LDSM4T(r0, r1, r2, r3, addr) \
    asm volatile("ldmatrix.sync.aligned.m8n8.x4.trans.shared.b16 {%0,%1,%2,%3}, [%4];" \
        : "=r"(r0), "=r"(r1), "=r"(r2), "=r"(r3) : "r"(addr))

// fp16 MMA
#define MMA16816F(d, a, b0v, b1v) \
    asm volatile("mma.sync.aligned.m16n8k16.row.col.f32.f16.f16.f32 " \
        "{%0,%1,%2,%3}, {%4,%5,%6,%7}, {%8,%9}, {%0,%1,%2,%3};" \
        : "+f"((d)[0]), "+f"((d)[1]), "+f"((d)[2]), "+f"((d)[3]) \
        : "r"((a)[0]), "r"((a)[1]), "r"((a)[2]), "r"((a)[3]), "r"(b0v), "r"(b1v))

__device__ __forceinline__ unsigned short f2h_bits(float f) {
    __half h = __float2half(f);
    return *reinterpret_cast<unsigned short*>(&h);
}
__device__ __forceinline__ void hsplit(float x, unsigned short& h, unsigned short& l) {
    h = f2h_bits(x);
    __half hb = *reinterpret_cast<__half*>(&h);
    l = f2h_bits(x - __half2float(hb));
}

// ---------------------------------------------------------------------------
// fp32 -> fp16 single-term conversion for activations. A[m, K].
// ---------------------------------------------------------------------------
__global__ __launch_bounds__(256) void convert_a_kernel(
    const float* __restrict__ X, unsigned short* __restrict__ A, int K)
{
    size_t idx = (size_t)blockIdx.x * blockDim.x + threadIdx.x;
    size_t total = (size_t)MM * K / 4;
    if (idx >= total) return;
    size_t e = idx * 4;
    float4 v = *(const float4*)(X + e);
    uint2 hp = make_uint2((uint32_t)f2h_bits(v.x) | ((uint32_t)f2h_bits(v.y) << 16),
                          (uint32_t)f2h_bits(v.z) | ((uint32_t)f2h_bits(v.w) << 16));
    *(uint2*)(A + e) = hp;
}

// ---------------------------------------------------------------------------
// W[K,N] fp32 -> B[N, K] fp16 (transposed).
// ---------------------------------------------------------------------------
__global__ __launch_bounds__(256) void convert_w_kernel(
    const float* __restrict__ W, unsigned short* __restrict__ Bm, int K, int N)
{
    __shared__ float tile[32][33];
    const int n0 = blockIdx.x * 32;
    const int k0 = blockIdx.y * 32;
    for (int i = threadIdx.y; i < 32; i += 8)
        tile[i][threadIdx.x] = W[(size_t)(k0 + i) * N + n0 + threadIdx.x];
    __syncthreads();
    for (int i = threadIdx.y; i < 32; i += 8) {
        const int n = n0 + i;
        const int k = k0 + threadIdx.x;
        Bm[(size_t)n * K + k] = f2h_bits(tile[threadIdx.x][i]);
    }
}

// ---------------------------------------------------------------------------
// mma.sync fp16 GEMM: BM=BN=128, BK=32, FOUR-stage cp.async (distance-3
// prefetch), 256 threads (8 warps 2x4, warp tile 64x32),
// __launch_bounds__(256, 2). Proven R12 loop order:
//   prefetch(c+3) -> commit -> wait_group 3 -> sync -> compute -> sync.
// C = A[M,K] @ B[N,K]^T + bias. Epilogue modes:
//   0: fp32 C = acc + bias                  -> Cf[m][N]
//   1: relu -> fp16                         -> Cs[m][N]
//   2: (acc+bias)*0.125 -> fp16 [hi|lo] [Q] -> Cs[m][2N]
//   3: fp16 [hi|hi]                     [K] -> Cs[m][2N]
//   4: fp16 single                      [V] -> Cs[m][N]
// ---------------------------------------------------------------------------
#define BK 32
#define NSTAGE 4
#define ROWB 80
#define B_OFF (128*ROWB)
#define STG_B (2*B_OFF)
#define GEMM_SMEM (NSTAGE*STG_B)    // 81920 (x2 CTAs = 160KB <= 228KB/SM)

__global__ __launch_bounds__(256, 2) void mma_gemm_kernel(
    const unsigned short* __restrict__ Au, const unsigned short* __restrict__ Bu,
    const float* __restrict__ bias, float* __restrict__ Cf,
    unsigned short* __restrict__ Cs, int N, int K2, int mode)
{
    extern __shared__ char smem[];
    const uint32_t sb = smem_u32(smem);
    const int tid = threadIdx.x;
    const int wid = tid >> 5, lane = tid & 31;
    const int wm = wid >> 2, wn = wid & 3;
    const int mb = blockIdx.y, nb = blockIdx.x;

    const int r0 = tid >> 2, cc = tid & 3;
    const unsigned short* aS = Au + ((size_t)(mb * 128) + r0) * K2 + cc * 8;
    const unsigned short* bS = Bu + ((size_t)(nb * 128) + r0) * K2 + cc * 8;
    const size_t rowskip = (size_t)64 * K2;
    const uint32_t dOff = (uint32_t)(r0 * ROWB + cc * 16);

    float acc[4][4][4];
    #pragma unroll
    for (int i = 0; i < 4; i++)
        #pragma unroll
        for (int j = 0; j < 4; j++)
            #pragma unroll
            for (int r = 0; r < 4; r++) acc[i][j][r] = 0.f;

    const int nc = K2 / BK;

    auto LOAD = [&](int s, int c) {
        const uint32_t d = sb + s * STG_B + dOff;
        const unsigned short* a = aS + (size_t)c * BK;
        const unsigned short* b = bS + (size_t)c * BK;
        cp16(d,                    a);
        cp16(d + 64 * ROWB,        a + rowskip);
        cp16(d + B_OFF,            b);
        cp16(d + B_OFF + 64*ROWB,  b + rowskip);
    };

    LOAD(0, 0); CP_COMMIT();
    LOAD(1, 1); CP_COMMIT();
    LOAD(2, 2); CP_COMMIT();

    const uint32_t aRow = (uint32_t)(wm * 64 + (lane & 15));
    const uint32_t aK   = ((lane >> 4) & 1) * 16;
    const uint32_t bRow = (uint32_t)(wn * 32 + ((lane >> 4) & 1) * 8 + (lane & 7));
    const uint32_t bK   = ((lane >> 3) & 1) * 16;

    for (int c = 0; c < nc; c++) {
        if (c + 3 < nc) LOAD((c + 3) & (NSTAGE - 1), c + 3);
        CP_COMMIT();
        CP_WAIT3();
        __syncthreads();
        const uint32_t base = sb + (c & (NSTAGE - 1)) * STG_B;
        #pragma unroll
        for (int ks = 0; ks < 2; ks++) {
            uint32_t af[4][4], bf[2][4];
            #pragma unroll
            for (int mt = 0; mt < 4; mt++) {
                const uint32_t ad = base + (aRow + mt * 16) * ROWB + ks * 32 + aK;
                LDSM4(af[mt][0], af[mt][1], af[mt][2], af[mt][3], ad);
            }
            #pragma unroll
            for (int j = 0; j < 2; j++) {
                const uint32_t bd = base + B_OFF + (bRow + j * 16) * ROWB + ks * 32 + bK;
                LDSM4(bf[j][0], bf[j][1], bf[j][2], bf[j][3], bd);
            }
            #pragma unroll
            for (int mt = 0; mt < 4; mt++)
                #pragma unroll
                for (int nt = 0; nt < 4; nt++)
                    MMA16816F(acc[mt][nt], af[mt],
                              bf[nt >> 1][(nt & 1) * 2], bf[nt >> 1][(nt & 1) * 2 + 1]);
        }
        __syncthreads();
    }

    // ---------------- epilogue (fused conversions) ----------------
    const int row0 = mb * 128 + wm * 64 + (lane >> 2);
    const int col0 = nb * 128 + wn * 32 + (lane & 3) * 2;
    #pragma unroll
    for (int mt = 0; mt < 4; mt++) {
        const int r1 = row0 + mt * 16;
        const int r2 = r1 + 8;
        #pragma unroll
        for (int nt = 0; nt < 4; nt++) {
            const int cn = col0 + nt * 8;
            const float bx = __ldg(bias + cn), by = __ldg(bias + cn + 1);
            float o10 = acc[mt][nt][0] + bx, o11 = acc[mt][nt][1] + by;
            float o20 = acc[mt][nt][2] + bx, o21 = acc[mt][nt][3] + by;
            if (mode == 0) {
                *(float2*)(Cf + (size_t)r1 * N + cn) = make_float2(o10, o11);
                *(float2*)(Cf + (size_t)r2 * N + cn) = make_float2(o20, o21);
            } else if (mode == 1) {
                o10 = fmaxf(o10, 0.f); o11 = fmaxf(o11, 0.f);
                o20 = fmaxf(o20, 0.f); o21 = fmaxf(o21, 0.f);
                *(uint32_t*)(Cs + (size_t)r1 * N + cn) =
                    (uint32_t)f2h_bits(o10) | ((uint32_t)f2h_bits(o11) << 16);
                *(uint32_t*)(Cs + (size_t)r2 * N + cn) =
                    (uint32_t)f2h_bits(o20) | ((uint32_t)f2h_bits(o21) << 16);
            } else if (mode == 4) {
                *(uint32_t*)(Cs + (size_t)r1 * N + cn) =
                    (uint32_t)f2h_bits(o10) | ((uint32_t)f2h_bits(o11) << 16);
                *(uint32_t*)(Cs + (size_t)r2 * N + cn) =
                    (uint32_t)f2h_bits(o20) | ((uint32_t)f2h_bits(o21) << 16);
            } else if (mode == 2) {
                o10 *= 0.125f; o11 *= 0.125f; o20 *= 0.125f; o21 *= 0.125f;
                unsigned short h0, l0, h1, l1;
                hsplit(o10, h0, l0); hsplit(o11, h1, l1);
                unsigned short* p = Cs + (size_t)r1 * (2 * N) + cn;
                *(uint32_t*)p       = (uint32_t)h0 | ((uint32_t)h1 << 16);
                *(uint32_t*)(p + N) = (uint32_t)l0 | ((uint32_t)l1 << 16);
                hsplit(o20, h0, l0); hsplit(o21, h1, l1);
                p = Cs + (size_t)r2 * (2 * N) + cn;
                *(uint32_t*)p       = (uint32_t)h0 | ((uint32_t)h1 << 16);
                *(uint32_t*)(p + N) = (uint32_t)l0 | ((uint32_t)l1 << 16);
            } else {
                uint32_t w1v = (uint32_t)f2h_bits(o10) | ((uint32_t)f2h_bits(o11) << 16);
                unsigned short* p = Cs + (size_t)r1 * (2 * N) + cn;
                *(uint32_t*)p       = w1v;
                *(uint32_t*)(p + N) = w1v;
                uint32_t w2v = (uint32_t)f2h_bits(o20) | ((uint32_t)f2h_bits(o21) << 16);
                p = Cs + (size_t)r2 * (2 * N) + cn;
                *(uint32_t*)p       = w2v;
                *(uint32_t*)(p + N) = w2v;
            }
        }
    }
}

// ---------------------------------------------------------------------------
// Tensor-core flash attention, fp16 2-term (unchanged from R12).
// ---------------------------------------------------------------------------
#define AQROWB 272
#define AVROWB 144
#define ATT2_SMEM (2*64*AQROWB + 64*AVROWB)   // 44032

__global__ __launch_bounds__(128, 2) void attn_tc_kernel(
    const unsigned short* __restrict__ Qg, const unsigned short* __restrict__ Kg,
    const unsigned short* __restrict__ Vg, unsigned short* __restrict__ Aout)
{
    extern __shared__ char sm8[];
    char* Qs = sm8;
    char* Ks = Qs + 64 * AQROWB;
    char* Vs = Ks + 64 * AQROWB;
    const uint32_t qsb = smem_u32(Qs), ksb = smem_u32(Ks);
    const uint32_t vsb = smem_u32(Vs);

    const int tid = threadIdx.x, wid = tid >> 5, lane = tid & 31;
    const int q0 = blockIdx.x * 64;
    const int b = blockIdx.y >> 4, h = blockIdx.y & 15;
    const size_t bS = (size_t)b * SS;

    {
        const int r = tid >> 1, half = tid & 1;
        const unsigned short* src = Qg + (bS + q0 + r) * (size_t)(2 * DD)
                                       + half * DD + h * 64;
        char* drow = Qs + r * AQROWB + half * 128;
        #pragma unroll
        for (int off = 0; off < 8; off++)
            *(uint4*)(drow + off * 16) = *(const uint4*)(src + off * 8);
    }
    __syncthreads();

    uint32_t qf[8][4];
    {
        const uint32_t ab = qsb + (wid * 16 + (lane & 15)) * AQROWB + ((lane >> 4) & 1) * 16;
        #pragma unroll
        for (int ks = 0; ks < 8; ks++)
            LDSM4(qf[ks][0], qf[ks][1], qf[ks][2], qf[ks][3], ab + ks * 32);
    }

    const uint32_t bRow = ((lane >> 4) & 1) * 8 + (lane & 7);
    const uint32_t bK   = ((lane >> 3) & 1) * 16;
    const uint32_t vLn  = (lane & 15);
    const uint32_t vCo  = ((lane >> 4) & 1) * 16;

    float O[8][4];
    #pragma unroll
    for (int j = 0; j < 8; j++)
        #pragma unroll
        for (int r = 0; r < 4; r++) O[j][r] = 0.f;
    float m0 = -1e30f, m1 = -1e30f, l0 = 0.f, l1 = 0.f;

    const int r0l = wid * 16 + (lane >> 2);
    const int r1l = r0l + 8;

    for (int kt = 0; kt <= blockIdx.x; kt++) {
        const int k0 = kt * 64;
        __syncthreads();
        {
            const int r = tid >> 1, half = tid & 1;
            const unsigned short* ksrc = Kg + (bS + k0 + r) * (size_t)(2 * DD)
                                            + half * DD + h * 64;
            char* krow = Ks + r * AQROWB + half * 128;
            #pragma unroll
            for (int off = 0; off < 8; off++)
                *(uint4*)(krow + off * 16) = *(const uint4*)(ksrc + off * 8);
            const unsigned short* vsrc = Vg + (bS + k0 + r) * (size_t)DD
                                            + h * 64 + half * 32;
            char* vrow = Vs + r * AVROWB + half * 64;
            #pragma unroll
            for (int off = 0; off < 4; off++)
                *(uint4*)(vrow + off * 16) = *(const uint4*)(vsrc + off * 8);
        }
        __syncthreads();

        float s[8][4];
        #pragma unroll
        for (int j = 0; j < 8; j++)
            #pragma unroll
            for (int r = 0; r < 4; r++) s[j][r] = 0.f;
        #pragma unroll
        for (int ks = 0; ks < 8; ks++) {
            #pragma unroll
            for (int j16 = 0; j16 < 4; j16++) {
                uint32_t kf0, kf1, kf2, kf3;
                LDSM4(kf0, kf1, kf2, kf3,
                      ksb + (j16 * 16 + bRow) * AQROWB + ks * 32 + bK);
                MMA16816F(s[2 * j16],     qf[ks], kf0, kf1);
                MMA16816F(s[2 * j16 + 1], qf[ks], kf2, kf3);
            }
        }

        if (kt == (int)blockIdx.x) {
            #pragma unroll
            for (int j = 0; j < 8; j++) {
                const int c = j * 8 + 2 * (lane & 3);
                if (c     > r0l) s[j][0] = -1e30f;
                if (c + 1 > r0l) s[j][1] = -1e30f;
                if (c     > r1l) s[j][2] = -1e30f;
                if (c + 1 > r1l) s[j][3] = -1e30f;
            }
        }

        float mx0 = -1e30f, mx1 = -1e30f;
        #pragma unroll
        for (int j = 0; j < 8; j++) {
            mx0 = fmaxf(mx0, fmaxf(s[j][0], s[j][1]));
            mx1 = fmaxf(mx1, fmaxf(s[j][2], s[j][3]));
        }
        mx0 = fmaxf(mx0, __shfl_xor_sync(0xffffffffu, mx0, 1));
        mx0 = fmaxf(mx0, __shfl_xor_sync(0xffffffffu, mx0, 2));
        mx1 = fmaxf(mx1, __shfl_xor_sync(0xffffffffu, mx1, 1));
        mx1 = fmaxf(mx1, __shfl_xor_sync(0xffffffffu, mx1, 2));
        const float mn0 = fmaxf(m0, mx0), mn1 = fmaxf(m1, mx1);
        const float cr0 = __expf(m0 - mn0), cr1 = __expf(m1 - mn1);
        m0 = mn0; m1 = mn1;
        float sum0 = 0.f, sum1 = 0.f;
        #pragma unroll
        for (int j = 0; j < 8; j++) {
            s[j][0] = __expf(s[j][0] - mn0);
            s[j][1] = __expf(s[j][1] - mn0);
            s[j][2] = __expf(s[j][2] - mn1);
            s[j][3] = __expf(s[j][3] - mn1);
            sum0 += s[j][0] + s[j][1];
            sum1 += s[j][2] + s[j][3];
        }
        sum0 += __shfl_xor_sync(0xffffffffu, sum0, 1);
        sum0 += __shfl_xor_sync(0xffffffffu, sum0, 2);
        sum1 += __shfl_xor_sync(0xffffffffu, sum1, 1);
        sum1 += __shfl_xor_sync(0xffffffffu, sum1, 2);
        l0 = l0 * cr0 + sum0;
        l1 = l1 * cr1 + sum1;
        #pragma unroll
        for (int j = 0; j < 8; j++) {
            O[j][0] *= cr0; O[j][1] *= cr0;
            O[j][2] *= cr1; O[j][3] *= cr1;
        }

        uint32_t phi[4][4], plo[4][4];
        #pragma unroll
        for (int ks2 = 0; ks2 < 4; ks2++) {
            const int j0 = 2 * ks2, j1 = j0 + 1;
            unsigned short h00, l00, h01, l01, h10, l10, h11, l11;
            hsplit(s[j0][0], h00, l00); hsplit(s[j0][1], h01, l01);
            phi[ks2][0] = (uint32_t)h00 | ((uint32_t)h01 << 16);
            plo[ks2][0] = (uint32_t)l00 | ((uint32_t)l01 << 16);
            hsplit(s[j0][2], h10, l10); hsplit(s[j0][3], h11, l11);
            phi[ks2][1] = (uint32_t)h10 | ((uint32_t)h11 << 16);
            plo[ks2][1] = (uint32_t)l10 | ((uint32_t)l11 << 16);
            hsplit(s[j1][0], h00, l00); hsplit(s[j1][1], h01, l01);
            phi[ks2][2] = (uint32_t)h00 | ((uint32_t)h01 << 16);
            plo[ks2][2] = (uint32_t)l00 | ((uint32_t)l01 << 16);
            hsplit(s[j1][2], h10, l10); hsplit(s[j1][3], h11, l11);
            phi[ks2][3] = (uint32_t)h10 | ((uint32_t)h11 << 16);
            plo[ks2][3] = (uint32_t)l10 | ((uint32_t)l11 << 16);
        }

        #pragma unroll
        for (int ks2 = 0; ks2 < 4; ks2++) {
            const uint32_t rowOff = (ks2 * 16 + vLn);
            #pragma unroll
            for (int dj = 0; dj < 4; dj++) {
                uint32_t v0, v1, v2, v3;
                LDSM4T(v0, v1, v2, v3, vsb + rowOff * AVROWB + dj * 32 + vCo);
                MMA16816F(O[2 * dj],     phi[ks2], v0, v1);
                MMA16816F(O[2 * dj + 1], phi[ks2], v2, v3);
                MMA16816F(O[2 * dj],     plo[ks2], v0, v1);
                MMA16816F(O[2 * dj + 1], plo[ks2], v2, v3);
            }
        }
    }

    const float inv0 = 1.f / l0, inv1 = 1.f / l1;
    const size_t m0g = bS + (q0 + r0l);
    const size_t m1g = m0g + 8;
    const int cb = h * 64 + 2 * (lane & 3);
    unsigned short* out0 = Aout + m0g * (size_t)DD + cb;
    unsigned short* out1 = Aout + m1g * (size_t)DD + cb;
    #pragma unroll
    for (int j = 0; j < 8; j++) {
        const int d = j * 8;
        *(uint32_t*)(out0 + d) = (uint32_t)f2h_bits(O[j][0] * inv0)
                               | ((uint32_t)f2h_bits(O[j][1] * inv0) << 16);
        *(uint32_t*)(out1 + d) = (uint32_t)f2h_bits(O[j][2] * inv1)
                               | ((uint32_t)f2h_bits(O[j][3] * inv1) << 16);
    }
}

// ---------------------------------------------------------------------------
// out = LayerNorm(x + y) * gamma + beta; optional fused fp16 conversion
// ---------------------------------------------------------------------------
__device__ __forceinline__ float block_sum(float v, float* sh)
{
    const int lane = threadIdx.x & 31, w = threadIdx.x >> 5;
    #pragma unroll
    for (int o = 16; o; o >>= 1) v += __shfl_xor_sync(0xffffffffu, v, o);
    if (lane == 0) sh[w] = v;
    __syncthreads();
    float r = (lane < 8) ? sh[lane] : 0.f;
    #pragma unroll
    for (int o = 4; o; o >>= 1) r += __shfl_xor_sync(0xffffffffu, r, o);
    if (threadIdx.x == 0) sh[0] = r;
    __syncthreads();
    r = sh[0];
    __syncthreads();
    return r;
}

__global__ __launch_bounds__(256) void add_ln_kernel(
    const float* __restrict__ X, const float* __restrict__ Y,
    const float* __restrict__ g, const float* __restrict__ bta,
    float* __restrict__ out, unsigned short* __restrict__ As)
{
    __shared__ float sh[32];
    const size_t row = blockIdx.x;
    const int t = threadIdx.x;
    const float4 xv = ((const float4*)(X + row * DD))[t];
    const float4 yv = ((const float4*)(Y + row * DD))[t];
    float v0 = xv.x + yv.x, v1 = xv.y + yv.y, v2 = xv.z + yv.z, v3 = xv.w + yv.w;
    const float mean = block_sum(v0 + v1 + v2 + v3, sh) * (1.f / DD);
    const float d0 = v0 - mean, d1 = v1 - mean, d2 = v2 - mean, d3 = v3 - mean;
    const float var = block_sum(d0*d0 + d1*d1 + d2*d2 + d3*d3, sh) * (1.f / DD);
    const float inv = rsqrtf(var + 1e-5f);
    const float4 gv = ((const float4*)g)[t];
    const float4 bv = ((const float4*)bta)[t];
    float4 o;
    o.x = d0 * inv * gv.x + bv.x;
    o.y = d1 * inv * gv.y + bv.y;
    o.z = d2 * inv * gv.z + bv.z;
    o.w = d3 * inv * gv.w + bv.w;
    ((float4*)(out + row * DD))[t] = o;
    if (As) {
        uint2 hp = make_uint2((uint32_t)f2h_bits(o.x) | ((uint32_t)f2h_bits(o.y) << 16),
                              (uint32_t)f2h_bits(o.z) | ((uint32_t)f2h_bits(o.w) << 16));
        *(uint2*)(As + row * (size_t)DD + t * 4) = hp;
    }
}

// ---------------------------------------------------------------------------
// Launcher
// ---------------------------------------------------------------------------
extern "C" void kernel_launch(void* const* d_in, const int* in_sizes, int n_in,
                              void* d_out, int out_size)
{
    (void)in_sizes; (void)n_in; (void)out_size;
    const float* x  = (const float*)d_in[0];
    const float* Wq = (const float*)d_in[2];
    const float* bq = (const float*)d_in[3];
    const float* Wk = (const float*)d_in[4];
    const float* bk = (const float*)d_in[5];
    const float* Wv = (const float*)d_in[6];
    const float* bv = (const float*)d_in[7];
    const float* Wo = (const float*)d_in[8];
    const float* bo = (const float*)d_in[9];
    const float* g1 = (const float*)d_in[10];
    const float* b1 = (const float*)d_in[11];
    const float* W1 = (const float*)d_in[12];
    const float* c1 = (const float*)d_in[13];
    const float* W2 = (const float*)d_in[14];
    const float* c2 = (const float*)d_in[15];
    const float* g2 = (const float*)d_in[16];
    const float* b2 = (const float*)d_in[17];
    float* out = (float*)d_out;

    float *proj, *x1, *ff2;
    cudaGetSymbolAddress((void**)&proj, g_proj);
    cudaGetSymbolAddress((void**)&x1,   g_x1);
    cudaGetSymbolAddress((void**)&ff2,  g_ff2);

    unsigned short *ax, *qs, *ks, *vs, *aatt, *ax1, *aff1;
    unsigned short *wq2, *wk2, *wv2, *wo2, *w12, *w22;
    cudaGetSymbolAddress((void**)&ax,   g_ax);
    cudaGetSymbolAddress((void**)&qs,   g_qs);
    cudaGetSymbolAddress((void**)&ks,   g_ks);
    cudaGetSymbolAddress((void**)&vs,   g_vs);
    cudaGetSymbolAddress((void**)&aatt, g_aatt);
    cudaGetSymbolAddress((void**)&ax1,  g_ax1);
    cudaGetSymbolAddress((void**)&aff1, g_aff1);
    cudaGetSymbolAddress((void**)&wq2,  g_wq);
    cudaGetSymbolAddress((void**)&wk2,  g_wk);
    cudaGetSymbolAddress((void**)&wv2,  g_wv);
    cudaGetSymbolAddress((void**)&wo2,  g_wo);
    cudaGetSymbolAddress((void**)&w12,  g_w1);
    cudaGetSymbolAddress((void**)&w22,  g_w2);

    cudaFuncSetAttribute(mma_gemm_kernel,
                         cudaFuncAttributeMaxDynamicSharedMemorySize, GEMM_SMEM);
    cudaFuncSetAttribute(attn_tc_kernel,
                         cudaFuncAttributeMaxDynamicSharedMemorySize, ATT2_SMEM);

    const dim3 blk(256);
    const dim3 wblk(32, 8);
    const dim3 gD(DD/128, MM/128);       // N=1024 GEMMs
    const dim3 gF(FF/128, MM/128);       // N=4096 GEMM

    convert_w_kernel<<<dim3(DD/32, DD/32), wblk>>>(Wq, wq2, DD, DD);
    convert_w_kernel<<<dim3(DD/32, DD/32), wblk>>>(Wk, wk2, DD, DD);
    convert_w_kernel<<<dim3(DD/32, DD/32), wblk>>>(Wv, wv2, DD, DD);
    convert_w_kernel<<<dim3(DD/32, DD/32), wblk>>>(Wo, wo2, DD, DD);
    convert_a_kernel<<<(int)(((size_t)MM*DD/4 + 255)/256), blk>>>(x, ax, DD);

    // QKV projections -> fp16 attention layouts
    mma_gemm_kernel<<<gD, blk, GEMM_SMEM>>>(ax, wq2, bq, nullptr, qs, DD, DD, 2);
    mma_gemm_kernel<<<gD, blk, GEMM_SMEM>>>(ax, wk2, bk, nullptr, ks, DD, DD, 3);
    mma_gemm_kernel<<<gD, blk, GEMM_SMEM>>>(ax, wv2, bv, nullptr, vs, DD, DD, 4);

    // attention (fp16 2-term, writes fp16 single A)
    attn_tc_kernel<<<dim3(SS/64, BB*HH), 128, ATT2_SMEM>>>(qs, ks, vs, aatt);

    // output projection + residual LN (fused fp16 conversion of x1)
    mma_gemm_kernel<<<gD, blk, GEMM_SMEM>>>(aatt, wo2, bo, proj, nullptr, DD, DD, 0);
    add_ln_kernel<<<MM, blk>>>(x, proj, g1, b1, x1, ax1);

    // FFN
    convert_w_kernel<<<dim3(FF/32, DD/32), wblk>>>(W1, w12, DD, FF);
    mma_gemm_kernel<<<gF, blk, GEMM_SMEM>>>(ax1, w12, c1, nullptr, aff1, FF, DD, 1);
    convert_w_kernel<<<dim3(DD/32, FF/32), wblk>>>(W2, w22, FF, DD);
    mma_gemm_kernel<<<gD, blk, GEMM_SMEM>>>(aff1, w22, c2, ff2, nullptr, DD, FF, 0);
    add_ln_kernel<<<MM, blk>>>(x1, ff2, g2, b2, out, nullptr);
}

// round 15
// speedup vs baseline: 1.2966x; 1.1621x over previous
#include <cuda_runtime.h>
#include <cuda_bf16.h>
#include <cuda_fp16.h>
#include <cstdint>
#include <cstddef>

// Problem constants
#define BB 4
#define SS 2048
#define DD 1024
#define HH 16
#define DKK 64
#define FF 4096
#define MM (BB*SS)          // 8192 rows

// ---------------------------------------------------------------------------
// Scratch (no allocations allowed -> __device__ globals)
// ---------------------------------------------------------------------------
__device__ float g_proj[(size_t)MM*DD];
__device__ float g_x1  [(size_t)MM*DD];
__device__ float g_ff2 [(size_t)MM*DD];

// fp16 single-term GEMM operands
__device__ unsigned short g_ax  [(size_t)MM*DD];     // x        fp16
__device__ unsigned short g_aatt[(size_t)MM*DD];     // attn out fp16
__device__ unsigned short g_ax1 [(size_t)MM*DD];     // x1       fp16
__device__ unsigned short g_aff1[(size_t)MM*FF];     // relu ff1 fp16
__device__ unsigned short g_wq  [(size_t)DD*DD];     // W^T fp16
__device__ unsigned short g_wk  [(size_t)DD*DD];
__device__ unsigned short g_wv  [(size_t)DD*DD];
__device__ unsigned short g_wo  [(size_t)DD*DD];
__device__ unsigned short g_w1  [(size_t)FF*DD];     // [N=F, K=D]
__device__ unsigned short g_w2  [(size_t)DD*FF];     // [N=D, K=F]

// attention operands
__device__ unsigned short g_qs  [(size_t)MM*2*DD];   // q*1/8 fp16 [hi | lo]
__device__ unsigned short g_ks  [(size_t)MM*DD];     // k     fp16 single
__device__ unsigned short g_vs  [(size_t)MM*DD];     // v     fp16 single

// ---------------------------------------------------------------------------
// Helpers
// ---------------------------------------------------------------------------
__device__ __forceinline__ uint32_t smem_u32(const void* p) {
    uint32_t a;
    asm("{ .reg .u64 t; cvta.to.shared.u64 t, %1; cvt.u32.u64 %0, t; }"
        : "=r"(a) : "l"(p));
    return a;
}

__device__ __forceinline__ void cp16(uint32_t dst, const void* src) {
    asm volatile("cp.async.cg.shared.global [%0], [%1], 16;" :: "r"(dst), "l"(src));
}

#define CP_COMMIT() asm volatile("cp.async.commit_group;")
#define CP_WAIT2()  asm volatile("cp.async.wait_group 2;" ::: "memory")

#define LDSM4(r0, r1, r2, r3, addr) \
    asm volatile("ldmatrix.sync.aligned.m8n8.x4.shared.b16 {%0,%1,%2,%3}, [%4];" \
        : "=r"(r0), "=r"(r1), "=r"(r2), "=r"(r3) : "r"(addr))

#define LDSM4T(r0, r1, r2, r3, addr) \
    asm volatile("ldmatrix.sync.aligned.m8n8.x4.trans.shared.b16 {%0,%1,%2,%3}, [%4];" \
        : "=r"(r0), "=r"(r1), "=r"(r2), "=r"(r3) : "r"(addr))

// fp16 MMA
#define MMA16816F(d, a, b0v, b1v) \
    asm volatile("mma.sync.aligned.m16n8k16.row.col.f32.f16.f16.f32 " \
        "{%0,%1,%2,%3}, {%4,%5,%6,%7}, {%8,%9}, {%0,%1,%2,%3};" \
        : "+f"((d)[0]), "+f"((d)[1]), "+f"((d)[2]), "+f"((d)[3]) \
        : "r"((a)[0]), "r"((a)[1]), "r"((a)[2]), "r"((a)[3]), "r"(b0v), "r"(b1v))

__device__ __forceinline__ unsigned short f2h_bits(float f) {
    __half h = __float2half(f);
    return *reinterpret_cast<unsigned short*>(&h);
}
__device__ __forceinline__ void hsplit(float x, unsigned short& h, unsigned short& l) {
    h = f2h_bits(x);
    __half hb = *reinterpret_cast<__half*>(&h);
    l = f2h_bits(x - __half2float(hb));
}

// ---------------------------------------------------------------------------
// fp32 -> fp16 single-term conversion for activations. A[m, K].
// ---------------------------------------------------------------------------
__global__ __launch_bounds__(256) void convert_a_kernel(
    const float* __restrict__ X, unsigned short* __restrict__ A, int K)
{
    size_t idx = (size_t)blockIdx.x * blockDim.x + threadIdx.x;
    size_t total = (size_t)MM * K / 4;
    if (idx >= total) return;
    size_t e = idx * 4;
    float4 v = *(const float4*)(X + e);
    uint2 hp = make_uint2((uint32_t)f2h_bits(v.x) | ((uint32_t)f2h_bits(v.y) << 16),
                          (uint32_t)f2h_bits(v.z) | ((uint32_t)f2h_bits(v.w) << 16));
    *(uint2*)(A + e) = hp;
}

// ---------------------------------------------------------------------------
// W[K,N] fp32 -> B[N, K] fp16 (transposed).
// ---------------------------------------------------------------------------
__global__ __launch_bounds__(256) void convert_w_kernel(
    const float* __restrict__ W, unsigned short* __restrict__ Bm, int K, int N)
{
    __shared__ float tile[32][33];
    const int n0 = blockIdx.x * 32;
    const int k0 = blockIdx.y * 32;
    for (int i = threadIdx.y; i < 32; i += 8)
        tile[i][threadIdx.x] = W[(size_t)(k0 + i) * N + n0 + threadIdx.x];
    __syncthreads();
    for (int i = threadIdx.y; i < 32; i += 8) {
        const int n = n0 + i;
        const int k = k0 + threadIdx.x;
        Bm[(size_t)n * K + k] = f2h_bits(tile[threadIdx.x][i]);
    }
}

// ---------------------------------------------------------------------------
// mma.sync fp16 GEMM: BM=BN=128, BK=32, 3-stage cp.async, 256 threads
// (8 warps 2x4, warp tile 64x32), __launch_bounds__(256, 2).
// EXACT R12 mainloop (best measured). Epilogue modes:
//   0: fp32 C = acc + bias                  -> Cf[m][N]
//   1: relu -> fp16                         -> Cs[m][N]
//   2: (acc+bias)*0.125 -> fp16 [hi|lo] [Q] -> Cs[m][2N]
//   4: fp16 single                    [K,V] -> Cs[m][N]
// ---------------------------------------------------------------------------
#define BK 32
#define NSTAGE 3
#define ROWB 80
#define B_OFF (128*ROWB)
#define STG_B (2*B_OFF)
#define GEMM_SMEM (NSTAGE*STG_B)    // 61440

__global__ __launch_bounds__(256, 2) void mma_gemm_kernel(
    const unsigned short* __restrict__ Au, const unsigned short* __restrict__ Bu,
    const float* __restrict__ bias, float* __restrict__ Cf,
    unsigned short* __restrict__ Cs, int N, int K2, int mode)
{
    extern __shared__ char smem[];
    const uint32_t sb = smem_u32(smem);
    const int tid = threadIdx.x;
    const int wid = tid >> 5, lane = tid & 31;
    const int wm = wid >> 2, wn = wid & 3;
    const int mb = blockIdx.y, nb = blockIdx.x;

    const int r0 = tid >> 2, cc = tid & 3;
    const unsigned short* aS = Au + ((size_t)(mb * 128) + r0) * K2 + cc * 8;
    const unsigned short* bS = Bu + ((size_t)(nb * 128) + r0) * K2 + cc * 8;
    const size_t rowskip = (size_t)64 * K2;
    const uint32_t dOff = (uint32_t)(r0 * ROWB + cc * 16);

    float acc[4][4][4];
    #pragma unroll
    for (int i = 0; i < 4; i++)
        #pragma unroll
        for (int j = 0; j < 4; j++)
            #pragma unroll
            for (int r = 0; r < 4; r++) acc[i][j][r] = 0.f;

    const int nc = K2 / BK;

    auto LOAD = [&](int s, int c) {
        const uint32_t d = sb + s * STG_B + dOff;
        const unsigned short* a = aS + (size_t)c * BK;
        const unsigned short* b = bS + (size_t)c * BK;
        cp16(d,                    a);
        cp16(d + 64 * ROWB,        a + rowskip);
        cp16(d + B_OFF,            b);
        cp16(d + B_OFF + 64*ROWB,  b + rowskip);
    };

    LOAD(0, 0); CP_COMMIT();
    LOAD(1, 1); CP_COMMIT();

    const uint32_t aRow = (uint32_t)(wm * 64 + (lane & 15));
    const uint32_t aK   = ((lane >> 4) & 1) * 16;
    const uint32_t bRow = (uint32_t)(wn * 32 + ((lane >> 4) & 1) * 8 + (lane & 7));
    const uint32_t bK   = ((lane >> 3) & 1) * 16;

    for (int c = 0; c < nc; c++) {
        if (c + 2 < nc) LOAD((c + 2) % NSTAGE, c + 2);
        CP_COMMIT();
        CP_WAIT2();
        __syncthreads();
        const uint32_t base = sb + (c % NSTAGE) * STG_B;
        #pragma unroll
        for (int ks = 0; ks < 2; ks++) {
            uint32_t af[4][4], bf[2][4];
            #pragma unroll
            for (int mt = 0; mt < 4; mt++) {
                const uint32_t ad = base + (aRow + mt * 16) * ROWB + ks * 32 + aK;
                LDSM4(af[mt][0], af[mt][1], af[mt][2], af[mt][3], ad);
            }
            #pragma unroll
            for (int j = 0; j < 2; j++) {
                const uint32_t bd = base + B_OFF + (bRow + j * 16) * ROWB + ks * 32 + bK;
                LDSM4(bf[j][0], bf[j][1], bf[j][2], bf[j][3], bd);
            }
            #pragma unroll
            for (int mt = 0; mt < 4; mt++)
                #pragma unroll
                for (int nt = 0; nt < 4; nt++)
                    MMA16816F(acc[mt][nt], af[mt],
                              bf[nt >> 1][(nt & 1) * 2], bf[nt >> 1][(nt & 1) * 2 + 1]);
        }
        __syncthreads();
    }

    // ---------------- epilogue (fused conversions) ----------------
    const int row0 = mb * 128 + wm * 64 + (lane >> 2);
    const int col0 = nb * 128 + wn * 32 + (lane & 3) * 2;
    #pragma unroll
    for (int mt = 0; mt < 4; mt++) {
        const int r1 = row0 + mt * 16;
        const int r2 = r1 + 8;
        #pragma unroll
        for (int nt = 0; nt < 4; nt++) {
            const int cn = col0 + nt * 8;
            const float bx = __ldg(bias + cn), by = __ldg(bias + cn + 1);
            float o10 = acc[mt][nt][0] + bx, o11 = acc[mt][nt][1] + by;
            float o20 = acc[mt][nt][2] + bx, o21 = acc[mt][nt][3] + by;
            if (mode == 0) {
                *(float2*)(Cf + (size_t)r1 * N + cn) = make_float2(o10, o11);
                *(float2*)(Cf + (size_t)r2 * N + cn) = make_float2(o20, o21);
            } else if (mode == 1) {
                o10 = fmaxf(o10, 0.f); o11 = fmaxf(o11, 0.f);
                o20 = fmaxf(o20, 0.f); o21 = fmaxf(o21, 0.f);
                *(uint32_t*)(Cs + (size_t)r1 * N + cn) =
                    (uint32_t)f2h_bits(o10) | ((uint32_t)f2h_bits(o11) << 16);
                *(uint32_t*)(Cs + (size_t)r2 * N + cn) =
                    (uint32_t)f2h_bits(o20) | ((uint32_t)f2h_bits(o21) << 16);
            } else if (mode == 4) {
                *(uint32_t*)(Cs + (size_t)r1 * N + cn) =
                    (uint32_t)f2h_bits(o10) | ((uint32_t)f2h_bits(o11) << 16);
                *(uint32_t*)(Cs + (size_t)r2 * N + cn) =
                    (uint32_t)f2h_bits(o20) | ((uint32_t)f2h_bits(o21) << 16);
            } else {
                // Q (mode 2): *0.125 -> fp16 [hi | lo]
                o10 *= 0.125f; o11 *= 0.125f; o20 *= 0.125f; o21 *= 0.125f;
                unsigned short h0, l0, h1, l1;
                hsplit(o10, h0, l0); hsplit(o11, h1, l1);
                unsigned short* p = Cs + (size_t)r1 * (2 * N) + cn;
                *(uint32_t*)p       = (uint32_t)h0 | ((uint32_t)h1 << 16);
                *(uint32_t*)(p + N) = (uint32_t)l0 | ((uint32_t)l1 << 16);
                hsplit(o20, h0, l0); hsplit(o21, h1, l1);
                p = Cs + (size_t)r2 * (2 * N) + cn;
                *(uint32_t*)p       = (uint32_t)h0 | ((uint32_t)h1 << 16);
                *(uint32_t*)(p + N) = (uint32_t)l0 | ((uint32_t)l1 << 16);
            }
        }
    }
}

// ---------------------------------------------------------------------------
// Tensor-core flash attention. Inputs:
//   Qg [m][2D]: fp16 [hi|lo] scaled 1/8; Kg [m][D]: fp16 single;
//   Vg [m][D]: fp16 single.
// S = (Qhi+Qlo)·K reusing each K fragment for both Q passes (half the K
// LDSM/smem of R12's duplicated-K scheme). P single fp16 -> 16 PV MMAs.
// Softmax in fp32. Epilogue writes fp16 single into g_aatt[m][D].
// ---------------------------------------------------------------------------
#define AQROWB 272                      // 256B data + 16B pad
#define AKROWB 144                      // 128B data + 16B pad
#define AVROWB 144
#define ATT2_SMEM (64*AQROWB + 64*AKROWB + 64*AVROWB)   // 35840

__global__ __launch_bounds__(128, 2) void attn_tc_kernel(
    const unsigned short* __restrict__ Qg, const unsigned short* __restrict__ Kg,
    const unsigned short* __restrict__ Vg, unsigned short* __restrict__ Aout)
{
    extern __shared__ char sm8[];
    char* Qs = sm8;
    char* Ks = Qs + 64 * AQROWB;
    char* Vs = Ks + 64 * AKROWB;
    const uint32_t qsb = smem_u32(Qs), ksb = smem_u32(Ks);
    const uint32_t vsb = smem_u32(Vs);

    const int tid = threadIdx.x, wid = tid >> 5, lane = tid & 31;
    const int q0 = blockIdx.x * 64;
    const int b = blockIdx.y >> 4, h = blockIdx.y & 15;
    const size_t bS = (size_t)b * SS;

    // ---- load Q tile: row = [hi(64) | lo(64)] fp16, 2 threads/row ----
    {
        const int r = tid >> 1, half = tid & 1;
        const unsigned short* src = Qg + (bS + q0 + r) * (size_t)(2 * DD)
                                       + half * DD + h * 64;
        char* drow = Qs + r * AQROWB + half * 128;
        #pragma unroll
        for (int off = 0; off < 8; off++)
            *(uint4*)(drow + off * 16) = *(const uint4*)(src + off * 8);
    }
    __syncthreads();

    // ---- Q fragments: ksteps 0-3 = hi, 4-7 = lo ----
    uint32_t qf[8][4];
    {
        const uint32_t ab = qsb + (wid * 16 + (lane & 15)) * AQROWB + ((lane >> 4) & 1) * 16;
        #pragma unroll
        for (int ks = 0; ks < 8; ks++)
            LDSM4(qf[ks][0], qf[ks][1], qf[ks][2], qf[ks][3], ab + ks * 32);
    }

    const uint32_t bRow = ((lane >> 4) & 1) * 8 + (lane & 7);
    const uint32_t bK   = ((lane >> 3) & 1) * 16;
    const uint32_t vLn  = (lane & 15);
    const uint32_t vCo  = ((lane >> 4) & 1) * 16;

    float O[8][4];
    #pragma unroll
    for (int j = 0; j < 8; j++)
        #pragma unroll
        for (int r = 0; r < 4; r++) O[j][r] = 0.f;
    float m0 = -1e30f, m1 = -1e30f, l0 = 0.f, l1 = 0.f;

    const int r0l = wid * 16 + (lane >> 2);
    const int r1l = r0l + 8;

    for (int kt = 0; kt <= blockIdx.x; kt++) {
        const int k0 = kt * 64;
        __syncthreads();
        // ---- load K tile (single, 4 chunks/thread-half) + V tile ----
        {
            const int r = tid >> 1, half = tid & 1;
            const unsigned short* ksrc = Kg + (bS + k0 + r) * (size_t)DD
                                            + h * 64 + half * 32;
            char* krow = Ks + r * AKROWB + half * 64;
            #pragma unroll
            for (int off = 0; off < 4; off++)
                *(uint4*)(krow + off * 16) = *(const uint4*)(ksrc + off * 8);
            const unsigned short* vsrc = Vg + (bS + k0 + r) * (size_t)DD
                                            + h * 64 + half * 32;
            char* vrow = Vs + r * AVROWB + half * 64;
            #pragma unroll
            for (int off = 0; off < 4; off++)
                *(uint4*)(vrow + off * 16) = *(const uint4*)(vsrc + off * 8);
        }
        __syncthreads();

        // ---- S = (Qhi + Qlo)·K^T, K fragments loaded once, used twice ----
        float s[8][4];
        #pragma unroll
        for (int j = 0; j < 8; j++)
            #pragma unroll
            for (int r = 0; r < 4; r++) s[j][r] = 0.f;
        #pragma unroll
        for (int ks = 0; ks < 4; ks++) {
            #pragma unroll
            for (int j16 = 0; j16 < 4; j16++) {
                uint32_t kf0, kf1, kf2, kf3;
                LDSM4(kf0, kf1, kf2, kf3,
                      ksb + (j16 * 16 + bRow) * AKROWB + ks * 32 + bK);
                MMA16816F(s[2 * j16],     qf[ks],     kf0, kf1);
                MMA16816F(s[2 * j16 + 1], qf[ks],     kf2, kf3);
                MMA16816F(s[2 * j16],     qf[ks + 4], kf0, kf1);
                MMA16816F(s[2 * j16 + 1], qf[ks + 4], kf2, kf3);
            }
        }

        // ---- causal mask (diagonal tile only) ----
        if (kt == (int)blockIdx.x) {
            #pragma unroll
            for (int j = 0; j < 8; j++) {
                const int c = j * 8 + 2 * (lane & 3);
                if (c     > r0l) s[j][0] = -1e30f;
                if (c + 1 > r0l) s[j][1] = -1e30f;
                if (c     > r1l) s[j][2] = -1e30f;
                if (c + 1 > r1l) s[j][3] = -1e30f;
            }
        }

        // ---- online softmax ----
        float mx0 = -1e30f, mx1 = -1e30f;
        #pragma unroll
        for (int j = 0; j < 8; j++) {
            mx0 = fmaxf(mx0, fmaxf(s[j][0], s[j][1]));
            mx1 = fmaxf(mx1, fmaxf(s[j][2], s[j][3]));
        }
        mx0 = fmaxf(mx0, __shfl_xor_sync(0xffffffffu, mx0, 1));
        mx0 = fmaxf(mx0, __shfl_xor_sync(0xffffffffu, mx0, 2));
        mx1 = fmaxf(mx1, __shfl_xor_sync(0xffffffffu, mx1, 1));
        mx1 = fmaxf(mx1, __shfl_xor_sync(0xffffffffu, mx1, 2));
        const float mn0 = fmaxf(m0, mx0), mn1 = fmaxf(m1, mx1);
        const float cr0 = __expf(m0 - mn0), cr1 = __expf(m1 - mn1);
        m0 = mn0; m1 = mn1;
        float sum0 = 0.f, sum1 = 0.f;
        #pragma unroll
        for (int j = 0; j < 8; j++) {
            s[j][0] = __expf(s[j][0] - mn0);
            s[j][1] = __expf(s[j][1] - mn0);
            s[j][2] = __expf(s[j][2] - mn1);
            s[j][3] = __expf(s[j][3] - mn1);
            sum0 += s[j][0] + s[j][1];
            sum1 += s[j][2] + s[j][3];
        }
        sum0 += __shfl_xor_sync(0xffffffffu, sum0, 1);
        sum0 += __shfl_xor_sync(0xffffffffu, sum0, 2);
        sum1 += __shfl_xor_sync(0xffffffffu, sum1, 1);
        sum1 += __shfl_xor_sync(0xffffffffu, sum1, 2);
        l0 = l0 * cr0 + sum0;
        l1 = l1 * cr1 + sum1;
        #pragma unroll
        for (int j = 0; j < 8; j++) {
            O[j][0] *= cr0; O[j][1] *= cr0;
            O[j][2] *= cr1; O[j][3] *= cr1;
        }

        // ---- P -> single fp16 A-fragments ----
        uint32_t phi[4][4];
        #pragma unroll
        for (int ks2 = 0; ks2 < 4; ks2++) {
            const int j0 = 2 * ks2, j1 = j0 + 1;
            phi[ks2][0] = (uint32_t)f2h_bits(s[j0][0]) | ((uint32_t)f2h_bits(s[j0][1]) << 16);
            phi[ks2][1] = (uint32_t)f2h_bits(s[j0][2]) | ((uint32_t)f2h_bits(s[j0][3]) << 16);
            phi[ks2][2] = (uint32_t)f2h_bits(s[j1][0]) | ((uint32_t)f2h_bits(s[j1][1]) << 16);
            phi[ks2][3] = (uint32_t)f2h_bits(s[j1][2]) | ((uint32_t)f2h_bits(s[j1][3]) << 16);
        }

        // ---- O += P·V ----
        #pragma unroll
        for (int ks2 = 0; ks2 < 4; ks2++) {
            const uint32_t rowOff = (ks2 * 16 + vLn);
            #pragma unroll
            for (int dj = 0; dj < 4; dj++) {
                uint32_t v0, v1, v2, v3;
                LDSM4T(v0, v1, v2, v3, vsb + rowOff * AVROWB + dj * 32 + vCo);
                MMA16816F(O[2 * dj],     phi[ks2], v0, v1);
                MMA16816F(O[2 * dj + 1], phi[ks2], v2, v3);
            }
        }
    }

    // ---- epilogue: O/l -> fp16 single rows of g_aatt ----
    const float inv0 = 1.f / l0, inv1 = 1.f / l1;
    const size_t m0g = bS + (q0 + r0l);
    const size_t m1g = m0g + 8;
    const int cb = h * 64 + 2 * (lane & 3);
    unsigned short* out0 = Aout + m0g * (size_t)DD + cb;
    unsigned short* out1 = Aout + m1g * (size_t)DD + cb;
    #pragma unroll
    for (int j = 0; j < 8; j++) {
        const int d = j * 8;
        *(uint32_t*)(out0 + d) = (uint32_t)f2h_bits(O[j][0] * inv0)
                               | ((uint32_t)f2h_bits(O[j][1] * inv0) << 16);
        *(uint32_t*)(out1 + d) = (uint32_t)f2h_bits(O[j][2] * inv1)
                               | ((uint32_t)f2h_bits(O[j][3] * inv1) << 16);
    }
}

// ---------------------------------------------------------------------------
// out = LayerNorm(x + y) * gamma + beta; optional fused fp16 conversion
// ---------------------------------------------------------------------------
__device__ __forceinline__ float block_sum(float v, float* sh)
{
    const int lane = threadIdx.x & 31, w = threadIdx.x >> 5;
    #pragma unroll
    for (int o = 16; o; o >>= 1) v += __shfl_xor_sync(0xffffffffu, v, o);
    if (lane == 0) sh[w] = v;
    __syncthreads();
    float r = (lane < 8) ? sh[lane] : 0.f;
    #pragma unroll
    for (int o = 4; o; o >>= 1) r += __shfl_xor_sync(0xffffffffu, r, o);
    if (threadIdx.x == 0) sh[0] = r;
    __syncthreads();
    r = sh[0];
    __syncthreads();
    return r;
}

__global__ __launch_bounds__(256) void add_ln_kernel(
    const float* __restrict__ X, const float* __restrict__ Y,
    const float* __restrict__ g, const float* __restrict__ bta,
    float* __restrict__ out, unsigned short* __restrict__ As)
{
    __shared__ float sh[32];
    const size_t row = blockIdx.x;
    const int t = threadIdx.x;
    const float4 xv = ((const float4*)(X + row * DD))[t];
    const float4 yv = ((const float4*)(Y + row * DD))[t];
    float v0 = xv.x + yv.x, v1 = xv.y + yv.y, v2 = xv.z + yv.z, v3 = xv.w + yv.w;
    const float mean = block_sum(v0 + v1 + v2 + v3, sh) * (1.f / DD);
    const float d0 = v0 - mean, d1 = v1 - mean, d2 = v2 - mean, d3 = v3 - mean;
    const float var = block_sum(d0*d0 + d1*d1 + d2*d2 + d3*d3, sh) * (1.f / DD);
    const float inv = rsqrtf(var + 1e-5f);
    const float4 gv = ((const float4*)g)[t];
    const float4 bv = ((const float4*)bta)[t];
    float4 o;
    o.x = d0 * inv * gv.x + bv.x;
    o.y = d1 * inv * gv.y + bv.y;
    o.z = d2 * inv * gv.z + bv.z;
    o.w = d3 * inv * gv.w + bv.w;
    ((float4*)(out + row * DD))[t] = o;
    if (As) {
        uint2 hp = make_uint2((uint32_t)f2h_bits(o.x) | ((uint32_t)f2h_bits(o.y) << 16),
                              (uint32_t)f2h_bits(o.z) | ((uint32_t)f2h_bits(o.w) << 16));
        *(uint2*)(As + row * (size_t)DD + t * 4) = hp;
    }
}

// ---------------------------------------------------------------------------
// Launcher
// ---------------------------------------------------------------------------
extern "C" void kernel_launch(void* const* d_in, const int* in_sizes, int n_in,
                              void* d_out, int out_size)
{
    (void)in_sizes; (void)n_in; (void)out_size;
    const float* x  = (const float*)d_in[0];
    const float* Wq = (const float*)d_in[2];
    const float* bq = (const float*)d_in[3];
    const float* Wk = (const float*)d_in[4];
    const float* bk = (const float*)d_in[5];
    const float* Wv = (const float*)d_in[6];
    const float* bv = (const float*)d_in[7];
    const float* Wo = (const float*)d_in[8];
    const float* bo = (const float*)d_in[9];
    const float* g1 = (const float*)d_in[10];
    const float* b1 = (const float*)d_in[11];
    const float* W1 = (const float*)d_in[12];
    const float* c1 = (const float*)d_in[13];
    const float* W2 = (const float*)d_in[14];
    const float* c2 = (const float*)d_in[15];
    const float* g2 = (const float*)d_in[16];
    const float* b2 = (const float*)d_in[17];
    float* out = (float*)d_out;

    float *proj, *x1, *ff2;
    cudaGetSymbolAddress((void**)&proj, g_proj);
    cudaGetSymbolAddress((void**)&x1,   g_x1);
    cudaGetSymbolAddress((void**)&ff2,  g_ff2);

    unsigned short *ax, *qs, *ks, *vs, *aatt, *ax1, *aff1;
    unsigned short *wq2, *wk2, *wv2, *wo2, *w12, *w22;
    cudaGetSymbolAddress((void**)&ax,   g_ax);
    cudaGetSymbolAddress((void**)&qs,   g_qs);
    cudaGetSymbolAddress((void**)&ks,   g_ks);
    cudaGetSymbolAddress((void**)&vs,   g_vs);
    cudaGetSymbolAddress((void**)&aatt, g_aatt);
    cudaGetSymbolAddress((void**)&ax1,  g_ax1);
    cudaGetSymbolAddress((void**)&aff1, g_aff1);
    cudaGetSymbolAddress((void**)&wq2,  g_wq);
    cudaGetSymbolAddress((void**)&wk2,  g_wk);
    cudaGetSymbolAddress((void**)&wv2,  g_wv);
    cudaGetSymbolAddress((void**)&wo2,  g_wo);
    cudaGetSymbolAddress((void**)&w12,  g_w1);
    cudaGetSymbolAddress((void**)&w22,  g_w2);

    cudaFuncSetAttribute(mma_gemm_kernel,
                         cudaFuncAttributeMaxDynamicSharedMemorySize, GEMM_SMEM);
    cudaFuncSetAttribute(attn_tc_kernel,
                         cudaFuncAttributeMaxDynamicSharedMemorySize, ATT2_SMEM);

    const dim3 blk(256);
    const dim3 wblk(32, 8);
    const dim3 gD(DD/128, MM/128);       // N=1024 GEMMs
    const dim3 gF(FF/128, MM/128);       // N=4096 GEMM

    convert_w_kernel<<<dim3(DD/32, DD/32), wblk>>>(Wq, wq2, DD, DD);
    convert_w_kernel<<<dim3(DD/32, DD/32), wblk>>>(Wk, wk2, DD, DD);
    convert_w_kernel<<<dim3(DD/32, DD/32), wblk>>>(Wv, wv2, DD, DD);
    convert_w_kernel<<<dim3(DD/32, DD/32), wblk>>>(Wo, wo2, DD, DD);
    convert_a_kernel<<<(int)(((size_t)MM*DD/4 + 255)/256), blk>>>(x, ax, DD);

    // QKV projections -> fp16 attention layouts (K and V single-term)
    mma_gemm_kernel<<<gD, blk, GEMM_SMEM>>>(ax, wq2, bq, nullptr, qs, DD, DD, 2);
    mma_gemm_kernel<<<gD, blk, GEMM_SMEM>>>(ax, wk2, bk, nullptr, ks, DD, DD, 4);
    mma_gemm_kernel<<<gD, blk, GEMM_SMEM>>>(ax, wv2, bv, nullptr, vs, DD, DD, 4);

    // attention (K-fragment reuse, single-term P)
    attn_tc_kernel<<<dim3(SS/64, BB*HH), 128, ATT2_SMEM>>>(qs, ks, vs, aatt);

    // output projection + residual LN (fused fp16 conversion of x1)
    mma_gemm_kernel<<<gD, blk, GEMM_SMEM>>>(aatt, wo2, bo, proj, nullptr, DD, DD, 0);
    add_ln_kernel<<<MM, blk>>>(x, proj, g1, b1, x1, ax1);

    // FFN
    convert_w_kernel<<<dim3(FF/32, DD/32), wblk>>>(W1, w12, DD, FF);
    mma_gemm_kernel<<<gF, blk, GEMM_SMEM>>>(ax1, w12, c1, nullptr, aff1, FF, DD, 1);
    convert_w_kernel<<<dim3(DD/32, FF/32), wblk>>>(W2, w22, FF, DD);
    mma_gemm_kernel<<<gD, blk, GEMM_SMEM>>>(aff1, w22, c2, ff2, nullptr, DD, FF, 0);
    add_ln_kernel<<<MM, blk>>>(x1, ff2, g2, b2, out, nullptr);
}